// round 1
// baseline (speedup 1.0000x reference)
#include <cuda_runtime.h>
#include <cstdint>

// Problem constants (fixed by setup_inputs)
#define T_N     2
#define PH      536            // patches_h == patches_w
#define HW      (PH*PH)        // 287296
#define OUTD    532            // cropped output H == W
#define PLANE   (OUTD*OUTD)    // 283024
#define PDIM    75
#define QW      36             // patch columns staged per strip (32 + 4)
#define SLOTS   6              // ring slots (5 live + 1 prefetch)
#define NTHR    128
#define YSEG    41             // rows per y-segment (13 segs * 41 >= 532)
#define NSEG    13
#define NSTRIP  17             // 17 * 32 >= 532

// Partial sums for per-(t,c) means: 2*3*32 chunks
__device__ float g_partials[T_N * 3 * 32];

// ---------------- means partial reduction ----------------
__global__ void means_kernel(const float* __restrict__ noisy) {
    int tc = blockIdx.x >> 5;          // 0..5
    int chunk = blockIdx.x & 31;       // 0..31
    const float* p = noisy + (size_t)tc * PLANE;
    float s = 0.f;
    for (int k = chunk * 256 + threadIdx.x; k < PLANE; k += 32 * 256)
        s += p[k];
    __shared__ float red[8];
    #pragma unroll
    for (int o = 16; o > 0; o >>= 1) s += __shfl_down_sync(0xffffffffu, s, o);
    if ((threadIdx.x & 31) == 0) red[threadIdx.x >> 5] = s;
    __syncthreads();
    if (threadIdx.x < 8) {
        s = red[threadIdx.x];
        #pragma unroll
        for (int o = 4; o > 0; o >>= 1) s += __shfl_down_sync(0xffu, s, o);
        if (threadIdx.x == 0) g_partials[blockIdx.x] = s;
    }
}

// ---------------- cp.async helpers ----------------
__device__ __forceinline__ void cpa4(float* d, const float* s) {
    uint32_t a = (uint32_t)__cvta_generic_to_shared(d);
    asm volatile("cp.async.ca.shared.global [%0], [%1], 4;\n" :: "r"(a), "l"(s));
}
__device__ __forceinline__ void cpa_commit() {
    asm volatile("cp.async.commit_group;\n" ::: "memory");
}
__device__ __forceinline__ void cpa_wait_all() {
    asm volatile("cp.async.wait_group 0;\n" ::: "memory");
}

// Stage one patch-row segment (qmax patches of 75 floats + weights) into a ring slot.
__device__ __forceinline__ void load_row(const float* __restrict__ deno,
                                         const float* __restrict__ pw,
                                         int t, int r, int x0, int qmax,
                                         float* dslot, float* wslot, int tid) {
    const float* src = deno + ((size_t)t * HW + (size_t)r * PH + x0) * PDIM;
    int nf = qmax * PDIM;
    for (int k = tid; k < nf; k += NTHR) cpa4(dslot + k, src + k);
    const float* wsrc = pw + (size_t)t * HW + (size_t)r * PH + x0;
    if (tid < qmax) cpa4(wslot + tid, wsrc + tid);
}

// ---------------- main fold kernel ----------------
__global__ void __launch_bounds__(NTHR) fold_kernel(const float* __restrict__ deno,
                                                    const float* __restrict__ pw,
                                                    float* __restrict__ out) {
    extern __shared__ float smem[];
    float* dS    = smem;                         // [SLOTS][QW][PDIM]
    float* wS    = smem + SLOTS * QW * PDIM;     // [SLOTS][QW]
    float* meanS = wS + SLOTS * QW;              // [3]

    const int tid = threadIdx.x;
    const int bx = blockIdx.x;      // x strip 0..16
    const int by = blockIdx.y;      // y segment 0..12
    const int t  = blockIdx.z;      // 0..1

    const int x0 = bx * 32;
    const int Y0 = by * YSEG;
    const int Y1 = min(Y0 + YSEG, OUTD);
    const int qmax = min(QW, PH - x0);

    // Preload 5 patch rows Y0..Y0+4
    #pragma unroll
    for (int a = 0; a < 5; ++a) {
        int r = Y0 + a;
        load_row(deno, pw, t, r, x0, qmax, dS + (r % SLOTS) * (QW * PDIM),
                 wS + (r % SLOTS) * QW, tid);
    }
    cpa_commit();

    // Finish means reduction (raw mean of noisy per (t,c))
    if (tid < 3) {
        float s = 0.f;
        #pragma unroll
        for (int k = 0; k < 32; ++k) s += g_partials[(t * 3 + tid) * 32 + k];
        meanS[tid] = s * (1.f / (float)PLANE);
    }
    cpa_wait_all();
    __syncthreads();

    const int c  = tid >> 5;        // warp id: 0,1,2 compute channels; warp 3 load-only
    const int Xl = tid & 31;
    const int X  = x0 + Xl;
    const bool act = (c < 3) && (X < OUTD);
    float* obase = out + (((size_t)t * 3 + c) * OUTD) * OUTD + X;

    for (int Y = Y0; Y < Y1; ++Y) {
        // Prefetch row Y+5 (rows needed up to Y1+3)
        int rn = Y + 5;
        if (rn <= Y1 + 3)
            load_row(deno, pw, t, rn, x0, qmax, dS + (rn % SLOTS) * (QW * PDIM),
                     wS + (rn % SLOTS) * QW, tid);
        cpa_commit();

        if (act) {
            float acc = 0.f, cnt = 0.f;
            #pragma unroll
            for (int a = 0; a < 5; ++a) {
                const float* ds = dS + ((Y + a) % SLOTS) * (QW * PDIM);
                const float* ws = wS + ((Y + a) % SLOTS) * QW;
                const int pbase = c * 25 + 24 - 5 * a;   // p = c*25 + (4-a)*5 + (4-b)
                #pragma unroll
                for (int b = 0; b < 5; ++b) {
                    float w = ws[Xl + b];
                    float v = ds[(Xl + b) * PDIM + (pbase - b)];
                    acc += v * w;
                    cnt += w;
                }
            }
            obase[(size_t)Y * OUTD] = 0.5f * acc / cnt + meanS[c];
        }

        cpa_wait_all();
        __syncthreads();
    }
}

extern "C" void kernel_launch(void* const* d_in, const int* in_sizes, int n_in,
                              void* d_out, int out_size) {
    const float* noisy = (const float*)d_in[0];
    const float* deno  = (const float*)d_in[1];
    const float* pw    = (const float*)d_in[2];
    // d_in[3] = inds : unused by the reference computation
    float* out = (float*)d_out;

    means_kernel<<<T_N * 3 * 32, 256>>>(noisy);

    size_t smem_bytes = (size_t)(SLOTS * QW * PDIM + SLOTS * QW + 4) * sizeof(float);
    cudaFuncSetAttribute(fold_kernel, cudaFuncAttributeMaxDynamicSharedMemorySize,
                         (int)smem_bytes);
    dim3 grid(NSTRIP, NSEG, T_N);
    fold_kernel<<<grid, NTHR, smem_bytes>>>(deno, pw, out);
}

// round 10
// speedup vs baseline: 1.4301x; 1.4301x over previous
// R10 = R2 kernel, ninth submission. R2: broker Trio-nursery ExceptionGroup;
// R3-R9: GPUAcquisitionTimeout (acmh18u at capacity). All failures are
// pre-compile/infra-side; the 16B-cp.async fold + float4 means variant has
// never executed on hardware. Source unchanged — single-change attribution
// preserved for the first successful bench. Pre-registered fork on that
// measurement: DRAM%>=75 -> traffic/redundancy work or accept ~30us floor;
// DRAM%~50 + wait/bar stalls -> rebalance pipeline within 3-CTA/SM smem.
#include <cuda_runtime.h>
#include <cstdint>

// Problem constants (fixed by setup_inputs)
#define T_N     2
#define PH      536            // patches_h == patches_w
#define HW      (PH*PH)        // 287296
#define OUTD    532            // cropped output H == W
#define PLANE   (OUTD*OUTD)    // 283024
#define PDIM    75
#define QW      36             // patch columns staged per strip (32 + 4)
#define SLOTS   6              // ring slots (5 live + 1 prefetch)
#define SLOTF   (QW*PDIM)      // 2700 floats per slot (16B aligned: 2700*4/16=675)
#define NTHR    128
#define YSEG    41             // rows per y-segment (13 segs * 41 >= 532)
#define NSEG    13
#define NSTRIP  17             // 17 * 32 >= 532
#define MCHUNK  64             // mean chunks per (t,c) plane

// Partial sums for per-(t,c) means: 6 planes * 64 chunks
__device__ float g_partials[T_N * 3 * MCHUNK];

// ---------------- means partial reduction (float4) ----------------
__global__ void means_kernel(const float* __restrict__ noisy) {
    int tc    = blockIdx.x >> 6;       // 0..5
    int chunk = blockIdx.x & (MCHUNK - 1);
    const float4* p = (const float4*)(noisy + (size_t)tc * PLANE);
    const int n4 = PLANE / 4;          // 70756 (exact)
    float s = 0.f;
    #pragma unroll 4
    for (int k = chunk * 256 + threadIdx.x; k < n4; k += MCHUNK * 256) {
        float4 v = p[k];
        s += (v.x + v.y) + (v.z + v.w);
    }
    __shared__ float red[8];
    #pragma unroll
    for (int o = 16; o > 0; o >>= 1) s += __shfl_down_sync(0xffffffffu, s, o);
    if ((threadIdx.x & 31) == 0) red[threadIdx.x >> 5] = s;
    __syncthreads();
    if (threadIdx.x < 8) {
        s = red[threadIdx.x];
        #pragma unroll
        for (int o = 4; o > 0; o >>= 1) s += __shfl_down_sync(0xffu, s, o);
        if (threadIdx.x == 0) g_partials[blockIdx.x] = s;
    }
}

// ---------------- cp.async helpers (16B) ----------------
__device__ __forceinline__ void cpa16(float* d, const float* s) {
    uint32_t a = (uint32_t)__cvta_generic_to_shared(d);
    asm volatile("cp.async.cg.shared.global [%0], [%1], 16;\n" :: "r"(a), "l"(s));
}
__device__ __forceinline__ void cpa_commit() {
    asm volatile("cp.async.commit_group;\n" ::: "memory");
}
__device__ __forceinline__ void cpa_wait_all() {
    asm volatile("cp.async.wait_group 0;\n" ::: "memory");
}

// Stage one patch-row segment (qmax patches of 75 floats + weights) into a ring slot.
// Base addresses are provably 16B-aligned and sizes divisible by 4 floats.
__device__ __forceinline__ void load_row(const float* __restrict__ deno,
                                         const float* __restrict__ pw,
                                         int t, int r, int x0, int qmax,
                                         float* dslot, float* wslot, int tid) {
    const float* src = deno + ((size_t)t * HW + (size_t)r * PH + x0) * PDIM;
    const int n16 = (qmax * PDIM) >> 2;   // 675 or 450
    #pragma unroll 4
    for (int k = tid; k < n16; k += NTHR) cpa16(dslot + 4 * k, src + 4 * k);
    const float* wsrc = pw + (size_t)t * HW + (size_t)r * PH + x0;
    if (tid < (qmax >> 2)) cpa16(wslot + 4 * tid, wsrc + 4 * tid);
}

// ---------------- main fold kernel ----------------
__global__ void __launch_bounds__(NTHR) fold_kernel(const float* __restrict__ deno,
                                                    const float* __restrict__ pw,
                                                    float* __restrict__ out) {
    extern __shared__ float smem[];
    float* dS    = smem;                        // [SLOTS][SLOTF]
    float* wS    = smem + SLOTS * SLOTF;        // [SLOTS][QW]
    float* meanS = wS + SLOTS * QW;             // [3]

    const int tid = threadIdx.x;
    const int bx = blockIdx.x;      // x strip 0..16
    const int by = blockIdx.y;      // y segment 0..12
    const int t  = blockIdx.z;      // 0..1

    const int x0 = bx * 32;
    const int Y0 = by * YSEG;
    const int Y1 = min(Y0 + YSEG, OUTD);
    const int qmax = min(QW, PH - x0);

    // Preload 5 patch rows Y0..Y0+4
    #pragma unroll
    for (int a = 0; a < 5; ++a) {
        int r = Y0 + a;
        load_row(deno, pw, t, r, x0, qmax, dS + (r % SLOTS) * SLOTF,
                 wS + (r % SLOTS) * QW, tid);
    }
    cpa_commit();

    // Finish means reduction (raw mean of noisy per (t,c))
    if (tid < 3) {
        float s = 0.f;
        #pragma unroll
        for (int k = 0; k < MCHUNK; ++k) s += g_partials[(t * 3 + tid) * MCHUNK + k];
        meanS[tid] = s * (1.f / (float)PLANE);
    }
    cpa_wait_all();
    __syncthreads();

    const int c  = tid >> 5;        // warp id: 0,1,2 compute channels; warp 3 load-only
    const int Xl = tid & 31;
    const int X  = x0 + Xl;
    const bool act = (c < 3) && (X < OUTD);
    float* obase = out + (((size_t)t * 3 + c) * OUTD) * OUTD + X;

    for (int Y = Y0; Y < Y1; ++Y) {
        // Prefetch row Y+5 (rows needed up to Y1+3)
        int rn = Y + 5;
        if (rn <= Y1 + 3)
            load_row(deno, pw, t, rn, x0, qmax, dS + (rn % SLOTS) * SLOTF,
                     wS + (rn % SLOTS) * QW, tid);
        cpa_commit();

        if (act) {
            float acc = 0.f, cnt = 0.f;
            #pragma unroll
            for (int a = 0; a < 5; ++a) {
                const float* ds = dS + ((Y + a) % SLOTS) * SLOTF;
                const float* ws = wS + ((Y + a) % SLOTS) * QW;
                const int pbase = c * 25 + 24 - 5 * a;   // p = c*25 + (4-a)*5 + (4-b)
                #pragma unroll
                for (int b = 0; b < 5; ++b) {
                    float w = ws[Xl + b];
                    float v = ds[(Xl + b) * PDIM + (pbase - b)];
                    acc += v * w;
                    cnt += w;
                }
            }
            obase[(size_t)Y * OUTD] = 0.5f * acc / cnt + meanS[c];
        }

        cpa_wait_all();
        __syncthreads();
    }
}

extern "C" void kernel_launch(void* const* d_in, const int* in_sizes, int n_in,
                              void* d_out, int out_size) {
    const float* noisy = (const float*)d_in[0];
    const float* deno  = (const float*)d_in[1];
    const float* pw    = (const float*)d_in[2];
    // d_in[3] = inds : unused by the reference computation
    float* out = (float*)d_out;

    means_kernel<<<T_N * 3 * MCHUNK, 256>>>(noisy);

    size_t smem_bytes = (size_t)(SLOTS * SLOTF + SLOTS * QW + 4) * sizeof(float);
    cudaFuncSetAttribute(fold_kernel, cudaFuncAttributeMaxDynamicSharedMemorySize,
                         (int)smem_bytes);
    dim3 grid(NSTRIP, NSEG, T_N);
    fold_kernel<<<grid, NTHR, smem_bytes>>>(deno, pw, out);
}